// round 5
// baseline (speedup 1.0000x reference)
#include <cuda_runtime.h>
#include <cuda_bf16.h>
#include <cstdint>
#include <math.h>

typedef unsigned long long ull;

#define FMA2(acc, a, b) asm("fma.rn.f32x2 %0, %1, %2, %0;" : "+l"(acc) : "l"(a), "l"(b))
#define PACK2(d, s)     asm("mov.b64 %0, {%1, %1};" : "=l"(d) : "f"(s))
#define UNPACK2(lo, hi, s) asm("mov.b64 {%0, %1}, %2;" : "=f"(lo), "=f"(hi) : "l"(s))
#define CP_ASYNC16(dst, src) \
    asm volatile("cp.async.cg.shared.global [%0], [%1], 16;" :: "r"(dst), "l"(src) : "memory")
#define CP_COMMIT()  asm volatile("cp.async.commit_group;" ::: "memory")
#define CP_WAIT6()   asm volatile("cp.async.wait_group 6;" ::: "memory")

constexpr int N    = 8192;
constexpr int FIN  = 512;
constexpr int FOUT = 128;
constexpr int NQ   = 512;    // number of k16 chunks (8192/16)
constexpr int NS   = 8;      // cp.async pipeline stages for adj

__device__ float  g_h[N * FOUT];
__device__ float4 g_hTf4[NQ * 16 * 4 * 8];   // B-fragment-ordered tf32 h^T (4MB)
__device__ float  g_E1[N], g_F1[N], g_E2[N], g_F2[N];

__device__ __forceinline__ float to_tf32(float x) {
    float r; asm("cvt.rna.tf32.f32 %0, %1;" : "=f"(r) : "f"(x)); return r;
}
__device__ __forceinline__ uint32_t smem_u32(const void* p) {
    return (uint32_t)__cvta_generic_to_shared(p);
}

// m16n8k8 tf32 warp MMA (sm_80+ PTX, works on base sm_103 target)
__device__ __forceinline__ void mma8(float* c, float a0, float a1, float a2, float a3,
                                     float b0, float b1) {
    asm volatile(
        "mma.sync.aligned.m16n8k8.row.col.f32.tf32.tf32.f32 "
        "{%0,%1,%2,%3}, {%4,%5,%6,%7}, {%8,%9}, {%0,%1,%2,%3};"
        : "+f"(c[0]), "+f"(c[1]), "+f"(c[2]), "+f"(c[3])
        : "r"(__float_as_uint(a0)), "r"(__float_as_uint(a1)),
          "r"(__float_as_uint(a2)), "r"(__float_as_uint(a3)),
          "r"(__float_as_uint(b0)), "r"(__float_as_uint(b1)));
}

__device__ __forceinline__ float elu_f(float v) { return v > 0.f ? v : expm1f(v); }

// ---------------------------------------------------------------------------
// Kernel A: h = X @ W  (fp32, packed f32x2 FMA), BM=64, grid 128.
// Also emits g_hTf4: tf32(h) in exact B-fragment order for the agg MMA:
//   j = 16q + 4lc + p  ->  float4 element p at index ((q*16 + f/8)*4 + lc)*8 + f%8
// ---------------------------------------------------------------------------
__global__ void __launch_bounds__(256) k_gemm_hw(const float* __restrict__ X,
                                                 const float* __restrict__ W) {
    __shared__ float sX[64][32];    // 8KB
    __shared__ float sB[32][FOUT];  // 16KB
    const int t = threadIdx.x;
    const int tx = t & 31, ty = t >> 5;   // tx: 4 cols, ty+8k: 8 rows
    const int m0 = blockIdx.x * 64;
    const int xr = t >> 2, xc0 = (t & 3) * 8;
    const int wr = t >> 3, wc0 = (t & 7) * 16;

    ull acc[8][2] = {};
    for (int kc = 0; kc < FIN / 32; ++kc) {
        const int k0 = kc * 32;
        __syncthreads();
        {
            float4*       dx = reinterpret_cast<float4*>(&sX[xr][xc0]);
            const float4* sx = reinterpret_cast<const float4*>(X + (size_t)(m0 + xr) * FIN + k0 + xc0);
            dx[0] = sx[0]; dx[1] = sx[1];
            float4*       dw = reinterpret_cast<float4*>(&sB[wr][wc0]);
            const float4* sw = reinterpret_cast<const float4*>(W + (size_t)(k0 + wr) * FOUT + wc0);
            dw[0] = sw[0]; dw[1] = sw[1]; dw[2] = sw[2]; dw[3] = sw[3];
        }
        __syncthreads();
        #pragma unroll 8
        for (int kk = 0; kk < 32; ++kk) {
            ulonglong2 b2 = *reinterpret_cast<const ulonglong2*>(&sB[kk][tx << 2]);
            #pragma unroll
            for (int k = 0; k < 8; ++k) {
                ull ap; PACK2(ap, sX[ty + 8 * k][kk]);
                FMA2(acc[k][0], ap, b2.x);
                FMA2(acc[k][1], ap, b2.y);
            }
        }
    }
    float* hTf = reinterpret_cast<float*>(g_hTf4);
    #pragma unroll
    for (int k = 0; k < 8; ++k) {
        const int r = m0 + ty + 8 * k;        // = j index for the agg GEMM
        float4 o;
        UNPACK2(o.x, o.y, acc[k][0]);
        UNPACK2(o.z, o.w, acc[k][1]);
        reinterpret_cast<float4*>(g_h + (size_t)r * FOUT)[tx] = o;
        const int q  = r >> 4;
        const int lc = (r >> 2) & 3;
        const int p  = r & 3;
        const float v[4] = {o.x, o.y, o.z, o.w};
        #pragma unroll
        for (int c = 0; c < 4; ++c) {
            const int f = tx * 4 + c;
            const int base = ((q * 16 + (f >> 3)) * 4 + lc) * 8 + (f & 7);
            hTf[base * 4 + p] = to_tf32(v[c]);
        }
    }
}

// ---------------------------------------------------------------------------
// Kernel B: E/F exp vectors from s = h@a1, h@a2
// ---------------------------------------------------------------------------
__global__ void __launch_bounds__(128) k_scores(const float* __restrict__ a) {
    const int i = blockIdx.x;
    const int t = threadIdx.x;
    const float hv = g_h[(size_t)i * FOUT + t];
    float p1 = hv * __ldg(&a[t]);
    float p2 = hv * __ldg(&a[FOUT + t]);
    #pragma unroll
    for (int off = 16; off; off >>= 1) {
        p1 += __shfl_xor_sync(0xffffffffu, p1, off);
        p2 += __shfl_xor_sync(0xffffffffu, p2, off);
    }
    __shared__ float r1[4], r2[4];
    const int w = t >> 5;
    if ((t & 31) == 0) { r1[w] = p1; r2[w] = p2; }
    __syncthreads();
    if (t == 0) {
        const float s1 = r1[0] + r1[1] + r1[2] + r1[3];
        const float s2 = r2[0] + r2[1] + r2[2] + r2[3];
        g_E1[i] = __expf(s1);  g_F1[i] = __expf(0.2f * s1);
        g_E2[i] = __expf(s2);  g_F2[i] = __expf(0.2f * s2);
    }
}

// ---------------------------------------------------------------------------
// Kernel C: masked-softmax aggregation as tf32 warp-MMA GEMM.
// grid 128 x (64 rows). 8 warps: 2(M) x 4(N); warp tile 32x32.
// adj streamed through an 8-stage cp.async smem ring (latency decoupling).
// Weights built in-register in A-fragment layout; w = adj ? max(E1E2, F1F2) : 0.
// Denominator = extra ones-column MMA on wid 3 (rows 0-31) / wid 4 (rows 32-63).
// ---------------------------------------------------------------------------
__global__ void __launch_bounds__(256, 1) k_agg(const int* __restrict__ adj,
                                                float* __restrict__ out) {
    extern __shared__ float smem[];
    float* sEF = smem;                                  // [0,8192)=E2, [8192,16384)=F2
    char*  ring = reinterpret_cast<char*>(smem + 2 * N); // 8 x 4KB adj stages
    __shared__ float sDen[64];

    const int t = threadIdx.x;
    const int lane = t & 31, wid = t >> 5;
    const int mw = wid >> 2, nw = wid & 3;
    const int lr = lane >> 2, lc = lane & 3;
    const int i0 = blockIdx.x * 64;
    const bool do_den = (wid == 3) || (wid == 4);

    // stage E2/F2 tables
    {
        const float4* e4 = reinterpret_cast<const float4*>(g_E2);
        const float4* f4 = reinterpret_cast<const float4*>(g_F2);
        float4* s4 = reinterpret_cast<float4*>(sEF);
        for (int k = t; k < N / 4; k += 256) {
            s4[k]         = e4[k];
            s4[N / 4 + k] = f4[k];
        }
    }

    // cp.async producer mapping: each thread copies one 16B segment per stage
    const int cprow = t >> 2, cpseg = t & 3;
    const int4* adj4 = reinterpret_cast<const int4*>(adj);
    const int4* cpsrc = adj4 + (size_t)(i0 + cprow) * (N / 4) + cpseg;
    const uint32_t cpdst = smem_u32(ring) + (uint32_t)(cprow * 64 + cpseg * 16);

    // prologue: stages 0 .. NS-2
    #pragma unroll
    for (int s = 0; s < NS - 1; ++s) {
        CP_ASYNC16(cpdst + s * 4096, cpsrc + s * 4);
        CP_COMMIT();
    }
    __syncthreads();   // sEF ready

    float e1[4], f1[4];
    #pragma unroll
    for (int k = 0; k < 4; ++k) {
        const int row = i0 + mw * 32 + lr + 8 * k;
        e1[k] = g_E1[row];
        f1[k] = g_F1[row];
    }
    const float4* sE4 = reinterpret_cast<const float4*>(sEF);
    const float4* sF4 = reinterpret_cast<const float4*>(sEF + N);

    float acc[2][4][4];
    #pragma unroll
    for (int mt = 0; mt < 2; ++mt)
        #pragma unroll
        for (int nt = 0; nt < 4; ++nt)
            #pragma unroll
            for (int r = 0; r < 4; ++r) acc[mt][nt][r] = 0.f;
    float den[2][4] = {};
    const float ob = (lr == 0) ? 1.0f : 0.0f;   // ones-column B fragment (col 0)

    // consumer smem addresses for adj (conflict-free LDS.128)
    const char* rd0 = ring + (mw * 32 + lr) * 64 + lc * 16;

    // depth-1 register prefetch for B fragments (L2-resident hT)
    float4 b4n[4];
    #pragma unroll
    for (int nt = 0; nt < 4; ++nt)
        b4n[nt] = __ldg(&g_hTf4[((nw * 4 + nt) * 4 + lc) * 8 + lr]);

    #pragma unroll 1
    for (int q = 0; q < NQ; ++q) {
        CP_WAIT6();
        __syncthreads();

        // read adj tile for this q from the ring
        const int slot = q & (NS - 1);
        int4 a4[4];
        #pragma unroll
        for (int k = 0; k < 4; ++k)
            a4[k] = *reinterpret_cast<const int4*>(rd0 + slot * 4096 + k * 512);

        // issue stage q+NS-1
        const int qn = q + NS - 1;
        if (qn < NQ) CP_ASYNC16(cpdst + (qn & (NS - 1)) * 4096, cpsrc + qn * 4);
        CP_COMMIT();

        // current B / E / F, prefetch next B
        float4 b4[4];
        #pragma unroll
        for (int nt = 0; nt < 4; ++nt) b4[nt] = b4n[nt];
        const float4 e4 = sE4[q * 4 + lc];
        const float4 f4 = sF4[q * 4 + lc];
        if (q + 1 < NQ) {
            #pragma unroll
            for (int nt = 0; nt < 4; ++nt)
                b4n[nt] = __ldg(&g_hTf4[(((q + 1) * 16 + nw * 4 + nt) * 4 + lc) * 8 + lr]);
        }

        // weights w[k][p]: row (lr + 8k within warp-M), j = 16q + 4lc + p
        float w[4][4];
        #pragma unroll
        for (int k = 0; k < 4; ++k) {
            const float ek = e1[k], fk = f1[k];
            w[k][0] = a4[k].x ? fmaxf(ek * e4.x, fk * f4.x) : 0.f;
            w[k][1] = a4[k].y ? fmaxf(ek * e4.y, fk * f4.y) : 0.f;
            w[k][2] = a4[k].z ? fmaxf(ek * e4.z, fk * f4.z) : 0.f;
            w[k][3] = a4[k].w ? fmaxf(ek * e4.w, fk * f4.w) : 0.f;
        }

        // k-step 0: j pair (p=0, p=1)
        #pragma unroll
        for (int mt = 0; mt < 2; ++mt) {
            const float a0 = w[2 * mt][0], a1 = w[2 * mt + 1][0];
            const float a2 = w[2 * mt][1], a3 = w[2 * mt + 1][1];
            #pragma unroll
            for (int nt = 0; nt < 4; ++nt)
                mma8(acc[mt][nt], a0, a1, a2, a3, b4[nt].x, b4[nt].y);
            if (do_den) mma8(den[mt], a0, a1, a2, a3, ob, ob);
        }
        // k-step 1: j pair (p=2, p=3)
        #pragma unroll
        for (int mt = 0; mt < 2; ++mt) {
            const float a0 = w[2 * mt][2], a1 = w[2 * mt + 1][2];
            const float a2 = w[2 * mt][3], a3 = w[2 * mt + 1][3];
            #pragma unroll
            for (int nt = 0; nt < 4; ++nt)
                mma8(acc[mt][nt], a0, a1, a2, a3, b4[nt].z, b4[nt].w);
            if (do_den) mma8(den[mt], a0, a1, a2, a3, ob, ob);
        }
    }

    // denominator: col 0 of den frags (lanes with lc==0). wid3 -> rows 0-31, wid4 -> rows 32-63.
    if (do_den && lc == 0) {
        sDen[mw * 32 + lr]      = den[0][0];
        sDen[mw * 32 + lr + 8]  = den[0][2];
        sDen[mw * 32 + lr + 16] = den[1][0];
        sDen[mw * 32 + lr + 24] = den[1][2];
    }
    __syncthreads();

    #pragma unroll
    for (int mt = 0; mt < 2; ++mt) {
        const int r0 = mw * 32 + mt * 16 + lr;
        const float inv0 = 1.f / sDen[r0];
        const float inv1 = 1.f / sDen[r0 + 8];
        #pragma unroll
        for (int nt = 0; nt < 4; ++nt) {
            const int col = nw * 32 + nt * 8 + lc * 2;
            float2 v0, v1;
            v0.x = elu_f(acc[mt][nt][0] * inv0);
            v0.y = elu_f(acc[mt][nt][1] * inv0);
            v1.x = elu_f(acc[mt][nt][2] * inv1);
            v1.y = elu_f(acc[mt][nt][3] * inv1);
            *reinterpret_cast<float2*>(out + (size_t)(i0 + r0) * FOUT + col)     = v0;
            *reinterpret_cast<float2*>(out + (size_t)(i0 + r0 + 8) * FOUT + col) = v1;
        }
    }
}

// ---------------------------------------------------------------------------
extern "C" void kernel_launch(void* const* d_in, const int* in_sizes, int n_in,
                              void* d_out, int out_size) {
    const float* X   = (const float*)d_in[0];   // 8192 x 512
    const int*   adj = (const int*)  d_in[1];   // 8192 x 8192
    const float* W   = (const float*)d_in[2];   // 512 x 128
    const float* a   = (const float*)d_in[3];   // 256 x 1
    float*       out = (float*)d_out;           // 8192 x 128

    cudaFuncSetAttribute(k_agg, cudaFuncAttributeMaxDynamicSharedMemorySize, 98304);

    k_gemm_hw<<<N / 64, 256>>>(X, W);
    k_scores<<<N, 128>>>(a);
    k_agg<<<N / 64, 256, 98304>>>(adj, out);
}

// round 6
// speedup vs baseline: 1.1581x; 1.1581x over previous
#include <cuda_runtime.h>
#include <cuda_fp16.h>
#include <cstdint>
#include <math.h>

typedef unsigned long long ull;

#define FMA2(acc, a, b) asm("fma.rn.f32x2 %0, %1, %2, %0;" : "+l"(acc) : "l"(a), "l"(b))
#define PACK2(d, s)     asm("mov.b64 %0, {%1, %1};" : "=l"(d) : "f"(s))
#define UNPACK2(lo, hi, s) asm("mov.b64 {%0, %1}, %2;" : "=f"(lo), "=f"(hi) : "l"(s))
#define CP_ASYNC16(dst, src) \
    asm volatile("cp.async.cg.shared.global [%0], [%1], 16;" :: "r"(dst), "l"(src) : "memory")
#define CP_COMMIT()  asm volatile("cp.async.commit_group;" ::: "memory")
#define CP_WAIT6()   asm volatile("cp.async.wait_group 6;" ::: "memory")

constexpr int N    = 8192;
constexpr int FIN  = 512;
constexpr int FOUT = 128;
constexpr int NQ   = 512;    // number of k16 chunks (8192/16)
constexpr int NS   = 8;      // cp.async pipeline stages for adj

__device__ float g_h[N * FOUT];
__device__ uint2 g_hTb[NQ * 16 * 4 * 8];     // fp16 B fragments of h^T (2MB, L2-resident)
__device__ float g_E1[N], g_F1[N], g_E2[N], g_F2[N];

__device__ __forceinline__ uint32_t smem_u32(const void* p) {
    return (uint32_t)__cvta_generic_to_shared(p);
}
__device__ __forceinline__ uint32_t pack_h2(float lo, float hi) {
    uint32_t r;  // d<15:0> = cvt(b=lo), d<31:16> = cvt(a=hi)
    asm("cvt.rn.f16x2.f32 %0, %1, %2;" : "=r"(r) : "f"(hi), "f"(lo));
    return r;
}

// m16n8k16 fp16 warp MMA, fp32 accumulate (sm_80+ PTX, valid at base sm_103)
__device__ __forceinline__ void mma16(float* c, uint32_t a0, uint32_t a1, uint32_t a2,
                                      uint32_t a3, uint32_t b0, uint32_t b1) {
    asm volatile(
        "mma.sync.aligned.m16n8k16.row.col.f32.f16.f16.f32 "
        "{%0,%1,%2,%3}, {%4,%5,%6,%7}, {%8,%9}, {%0,%1,%2,%3};"
        : "+f"(c[0]), "+f"(c[1]), "+f"(c[2]), "+f"(c[3])
        : "r"(a0), "r"(a1), "r"(a2), "r"(a3), "r"(b0), "r"(b1));
}

__device__ __forceinline__ float elu_f(float v) { return v > 0.f ? v : expm1f(v); }

// ---------------------------------------------------------------------------
// Kernel A: h = X @ W  (fp32, packed f32x2 FMA), BM=64, grid 128.
// Also emits g_hTb: fp16(h) in exact m16n8k16 B-fragment order:
//   j = 16q + 4lc + p, f = fgrp*8 + fl  ->  half index (((q*16+fgrp)*4+lc)*8+fl)*4 + p
// ---------------------------------------------------------------------------
__global__ void __launch_bounds__(256) k_gemm_hw(const float* __restrict__ X,
                                                 const float* __restrict__ W) {
    __shared__ float sX[64][32];    // 8KB
    __shared__ float sB[32][FOUT];  // 16KB
    const int t = threadIdx.x;
    const int tx = t & 31, ty = t >> 5;   // tx: 4 cols, ty+8k: 8 rows
    const int m0 = blockIdx.x * 64;
    const int xr = t >> 2, xc0 = (t & 3) * 8;
    const int wr = t >> 3, wc0 = (t & 7) * 16;

    ull acc[8][2] = {};
    for (int kc = 0; kc < FIN / 32; ++kc) {
        const int k0 = kc * 32;
        __syncthreads();
        {
            float4*       dx = reinterpret_cast<float4*>(&sX[xr][xc0]);
            const float4* sx = reinterpret_cast<const float4*>(X + (size_t)(m0 + xr) * FIN + k0 + xc0);
            dx[0] = sx[0]; dx[1] = sx[1];
            float4*       dw = reinterpret_cast<float4*>(&sB[wr][wc0]);
            const float4* sw = reinterpret_cast<const float4*>(W + (size_t)(k0 + wr) * FOUT + wc0);
            dw[0] = sw[0]; dw[1] = sw[1]; dw[2] = sw[2]; dw[3] = sw[3];
        }
        __syncthreads();
        #pragma unroll 8
        for (int kk = 0; kk < 32; ++kk) {
            ulonglong2 b2 = *reinterpret_cast<const ulonglong2*>(&sB[kk][tx << 2]);
            #pragma unroll
            for (int k = 0; k < 8; ++k) {
                ull ap; PACK2(ap, sX[ty + 8 * k][kk]);
                FMA2(acc[k][0], ap, b2.x);
                FMA2(acc[k][1], ap, b2.y);
            }
        }
    }
    __half* hTb = reinterpret_cast<__half*>(g_hTb);
    #pragma unroll
    for (int k = 0; k < 8; ++k) {
        const int r = m0 + ty + 8 * k;        // = j index for the agg GEMM
        float4 o;
        UNPACK2(o.x, o.y, acc[k][0]);
        UNPACK2(o.z, o.w, acc[k][1]);
        reinterpret_cast<float4*>(g_h + (size_t)r * FOUT)[tx] = o;
        const int q  = r >> 4;
        const int lc = (r >> 2) & 3;
        const int p  = r & 3;
        const float v[4] = {o.x, o.y, o.z, o.w};
        #pragma unroll
        for (int c = 0; c < 4; ++c) {
            const int f = tx * 4 + c;
            const int idx = (((q * 16 + (f >> 3)) * 4 + lc) * 8 + (f & 7)) * 4 + p;
            hTb[idx] = __float2half_rn(v[c]);
        }
    }
}

// ---------------------------------------------------------------------------
// Kernel B: E/F exp vectors from s = h@a1, h@a2
// ---------------------------------------------------------------------------
__global__ void __launch_bounds__(128) k_scores(const float* __restrict__ a) {
    const int i = blockIdx.x;
    const int t = threadIdx.x;
    const float hv = g_h[(size_t)i * FOUT + t];
    float p1 = hv * __ldg(&a[t]);
    float p2 = hv * __ldg(&a[FOUT + t]);
    #pragma unroll
    for (int off = 16; off; off >>= 1) {
        p1 += __shfl_xor_sync(0xffffffffu, p1, off);
        p2 += __shfl_xor_sync(0xffffffffu, p2, off);
    }
    __shared__ float r1[4], r2[4];
    const int w = t >> 5;
    if ((t & 31) == 0) { r1[w] = p1; r2[w] = p2; }
    __syncthreads();
    if (t == 0) {
        const float s1 = r1[0] + r1[1] + r1[2] + r1[3];
        const float s2 = r2[0] + r2[1] + r2[2] + r2[3];
        g_E1[i] = __expf(s1);  g_F1[i] = __expf(0.2f * s1);
        g_E2[i] = __expf(s2);  g_F2[i] = __expf(0.2f * s2);
    }
}

// ---------------------------------------------------------------------------
// Kernel C: masked-softmax aggregation as fp16 m16n8k16 warp-MMA GEMM.
// grid 128 x (64 rows). 8 warps: 2(M) x 4(N); warp tile 32x32.
// adj streamed through an 8-stage cp.async smem ring.
// Weights computed in fp32, rounded once to fp16 into A fragments;
// denominator = ones-column MMA on same fragments (rounding cancels in ratio).
// ---------------------------------------------------------------------------
__global__ void __launch_bounds__(256, 1) k_agg(const int* __restrict__ adj,
                                                float* __restrict__ out) {
    extern __shared__ float smem[];
    float* sEF = smem;                                   // [0,8192)=E2, [8192,16384)=F2
    char*  ring = reinterpret_cast<char*>(smem + 2 * N); // 8 x 4KB adj stages
    __shared__ float sDen[64];

    const int t = threadIdx.x;
    const int lane = t & 31, wid = t >> 5;
    const int mw = wid >> 2, nw = wid & 3;
    const int lr = lane >> 2, lc = lane & 3;
    const int i0 = blockIdx.x * 64;
    const bool do_den = (wid == 3) || (wid == 4);

    // stage E2/F2 tables (fp32: keeps logit noise down; final rnd16 cancels in ratio)
    {
        const float4* e4 = reinterpret_cast<const float4*>(g_E2);
        const float4* f4 = reinterpret_cast<const float4*>(g_F2);
        float4* s4 = reinterpret_cast<float4*>(sEF);
        for (int k = t; k < N / 4; k += 256) {
            s4[k]         = e4[k];
            s4[N / 4 + k] = f4[k];
        }
    }

    // cp.async producer mapping: each thread copies one 16B segment per stage
    const int cprow = t >> 2, cpseg = t & 3;
    const int4* adj4 = reinterpret_cast<const int4*>(adj);
    const int4* cpsrc = adj4 + (size_t)(i0 + cprow) * (N / 4) + cpseg;
    const uint32_t cpdst = smem_u32(ring) + (uint32_t)(cprow * 64 + cpseg * 16);

    #pragma unroll
    for (int s = 0; s < NS - 1; ++s) {
        CP_ASYNC16(cpdst + s * 4096, cpsrc + s * 4);
        CP_COMMIT();
    }
    __syncthreads();   // sEF ready

    float e1[4], f1[4];
    #pragma unroll
    for (int k = 0; k < 4; ++k) {
        const int row = i0 + mw * 32 + lr + 8 * k;
        e1[k] = g_E1[row];
        f1[k] = g_F1[row];
    }
    const float4* sE4 = reinterpret_cast<const float4*>(sEF);
    const float4* sF4 = reinterpret_cast<const float4*>(sEF + N);

    float acc[2][4][4];
    #pragma unroll
    for (int mt = 0; mt < 2; ++mt)
        #pragma unroll
        for (int nt = 0; nt < 4; ++nt)
            #pragma unroll
            for (int r = 0; r < 4; ++r) acc[mt][nt][r] = 0.f;
    float den[2][4] = {};
    const uint32_t bden = (lr == 0) ? 0x3C003C00u : 0u;   // ones in B col 0 (all k slots)

    // consumer smem addresses for adj (conflict-free LDS.128)
    const char* rd0 = ring + (mw * 32 + lr) * 64 + lc * 16;

    // depth-1 register prefetch for B fragments (L2-resident, 2MB)
    uint2 b2n[4];
    #pragma unroll
    for (int nt = 0; nt < 4; ++nt)
        b2n[nt] = __ldg(&g_hTb[((nw * 4 + nt) * 4 + lc) * 8 + lr]);

    #pragma unroll 1
    for (int q = 0; q < NQ; ++q) {
        CP_WAIT6();
        __syncthreads();

        // read adj tile for this q from the ring
        const int slot = q & (NS - 1);
        int4 a4[4];
        #pragma unroll
        for (int k = 0; k < 4; ++k)
            a4[k] = *reinterpret_cast<const int4*>(rd0 + slot * 4096 + k * 512);

        // issue stage q+NS-1
        const int qn = q + NS - 1;
        if (qn < NQ) CP_ASYNC16(cpdst + (qn & (NS - 1)) * 4096, cpsrc + qn * 4);
        CP_COMMIT();

        // current B / E / F, prefetch next B
        uint2 b2[4];
        #pragma unroll
        for (int nt = 0; nt < 4; ++nt) b2[nt] = b2n[nt];
        const float4 e4 = sE4[q * 4 + lc];
        const float4 f4 = sF4[q * 4 + lc];
        if (q + 1 < NQ) {
            #pragma unroll
            for (int nt = 0; nt < 4; ++nt)
                b2n[nt] = __ldg(&g_hTb[(((q + 1) * 16 + nw * 4 + nt) * 4 + lc) * 8 + lr]);
        }

        // weights w[k][p] (fp32): row (lr + 8k within CTA half), j = 16q + 4lc + p
        float w[4][4];
        #pragma unroll
        for (int k = 0; k < 4; ++k) {
            const float ek = e1[k], fk = f1[k];
            w[k][0] = a4[k].x ? fmaxf(ek * e4.x, fk * f4.x) : 0.f;
            w[k][1] = a4[k].y ? fmaxf(ek * e4.y, fk * f4.y) : 0.f;
            w[k][2] = a4[k].z ? fmaxf(ek * e4.z, fk * f4.z) : 0.f;
            w[k][3] = a4[k].w ? fmaxf(ek * e4.w, fk * f4.w) : 0.f;
        }

        // pack fp16 A fragments and issue MMAs (k16 covers whole chunk)
        #pragma unroll
        for (int mt = 0; mt < 2; ++mt) {
            const uint32_t af0 = pack_h2(w[2 * mt][0],     w[2 * mt][1]);     // row lr,   k 2lc,2lc+1
            const uint32_t af1 = pack_h2(w[2 * mt + 1][0], w[2 * mt + 1][1]); // row lr+8
            const uint32_t af2 = pack_h2(w[2 * mt][2],     w[2 * mt][3]);     // row lr,   k 2lc+8,+9
            const uint32_t af3 = pack_h2(w[2 * mt + 1][2], w[2 * mt + 1][3]); // row lr+8
            #pragma unroll
            for (int nt = 0; nt < 4; ++nt)
                mma16(acc[mt][nt], af0, af1, af2, af3, b2[nt].x, b2[nt].y);
            if (do_den) mma16(den[mt], af0, af1, af2, af3, bden, bden);
        }
    }

    // denominator: col 0 of den frags (lanes with lc==0). wid3 -> rows 0-31, wid4 -> 32-63.
    if (do_den && lc == 0) {
        sDen[mw * 32 + lr]      = den[0][0];
        sDen[mw * 32 + lr + 8]  = den[0][2];
        sDen[mw * 32 + lr + 16] = den[1][0];
        sDen[mw * 32 + lr + 24] = den[1][2];
    }
    __syncthreads();

    #pragma unroll
    for (int mt = 0; mt < 2; ++mt) {
        const int r0 = mw * 32 + mt * 16 + lr;
        const float inv0 = 1.f / sDen[r0];
        const float inv1 = 1.f / sDen[r0 + 8];
        #pragma unroll
        for (int nt = 0; nt < 4; ++nt) {
            const int col = nw * 32 + nt * 8 + lc * 2;
            float2 v0, v1;
            v0.x = elu_f(acc[mt][nt][0] * inv0);
            v0.y = elu_f(acc[mt][nt][1] * inv0);
            v1.x = elu_f(acc[mt][nt][2] * inv1);
            v1.y = elu_f(acc[mt][nt][3] * inv1);
            *reinterpret_cast<float2*>(out + (size_t)(i0 + r0) * FOUT + col)     = v0;
            *reinterpret_cast<float2*>(out + (size_t)(i0 + r0 + 8) * FOUT + col) = v1;
        }
    }
}

// ---------------------------------------------------------------------------
extern "C" void kernel_launch(void* const* d_in, const int* in_sizes, int n_in,
                              void* d_out, int out_size) {
    const float* X   = (const float*)d_in[0];   // 8192 x 512
    const int*   adj = (const int*)  d_in[1];   // 8192 x 8192
    const float* W   = (const float*)d_in[2];   // 512 x 128
    const float* a   = (const float*)d_in[3];   // 256 x 1
    float*       out = (float*)d_out;           // 8192 x 128

    cudaFuncSetAttribute(k_agg, cudaFuncAttributeMaxDynamicSharedMemorySize, 98304);

    k_gemm_hw<<<N / 64, 256>>>(X, W);
    k_scores<<<N, 128>>>(a);
    k_agg<<<N / 64, 256, 98304>>>(adj, out);
}